// round 2
// baseline (speedup 1.0000x reference)
#include <cuda_runtime.h>

#define NSENT 4000
#define LSEQ  128
#define EMBD  60
#define HID   230
#define HIDP  232      // padded channels (29 chunks of 8)
#define NBAG  500
#define NREL  25
#define TT    180      // EMB * 3 (reduction length)
#define ESTRIDE 61     // smem row stride (coprime with 32 -> conflict-free)

typedef unsigned long long u64;

// Scratch (device globals; no runtime allocation allowed)
__device__ __align__(16) float g_wT[TT * HIDP];    // transposed, padded conv weights: wT[t][c]
__device__ float g_h[NSENT * HIDP];                // pooled sentence features

// ---------------------------------------------------------------------------
// Prep: transpose conv_w [HID][EMB][3] -> wT[t=d*3+k][c], zero-pad c in [230,232)
// ---------------------------------------------------------------------------
__global__ void prep_w_kernel(const float* __restrict__ conv_w) {
    int i = blockIdx.x * blockDim.x + threadIdx.x;
    if (i >= TT * HIDP) return;
    int t = i / HIDP, c = i - t * HIDP;
    g_wT[i] = (c < HID) ? conv_w[c * TT + t] : 0.f;
}

// packed fp32x2 helpers --------------------------------------------------------
__device__ __forceinline__ u64 splat_f32x2(float v) {
    u64 r;
    asm("mov.b64 %0, {%1, %1};" : "=l"(r) : "f"(v));
    return r;
}
__device__ __forceinline__ void ffma2(u64& acc, u64 a, u64 b) {
    asm("fma.rn.f32x2 %0, %1, %2, %0;" : "+l"(acc) : "l"(a), "l"(b));
}
__device__ __forceinline__ void unpack2(u64 v, float& lo, float& hi) {
    asm("mov.b64 {%0, %1}, %2;" : "=f"(lo), "=f"(hi) : "l"(v));
}

// ---------------------------------------------------------------------------
// Fused: embedding gather + conv1d(k=3, SAME) + maxpool over L + bias + relu
// One block per sentence. 8 warps: lane -> 4 positions, warp -> 8-channel chunks.
// Inner product runs on packed fp32x2 (FFMA2) — 2 MACs per fma-pipe slot.
// ---------------------------------------------------------------------------
__global__ __launch_bounds__(256, 2) void conv_kernel(
    const int*   __restrict__ X,
    const int*   __restrict__ P1,
    const int*   __restrict__ P2,
    const float* __restrict__ WE,   // [50002][50]
    const float* __restrict__ E1,   // [201][5]
    const float* __restrict__ E2,   // [201][5]
    const float* __restrict__ conv_b)
{
    __shared__ float es[130 * ESTRIDE];   // rows 0..129 = positions -1..128 (zero-padded ends)
    const int n = blockIdx.x;

    // Gather embeddings into smem (rows 1..128); zero pad rows 0 and 129.
    for (int i = threadIdx.x; i < LSEQ * EMBD; i += 256) {
        int l = i / EMBD, d = i - l * EMBD;
        float v;
        if (d < 50)      v = WE[X[n * LSEQ + l] * 50 + d];
        else if (d < 55) v = E1[P1[n * LSEQ + l] * 5 + (d - 50)];
        else             v = E2[P2[n * LSEQ + l] * 5 + (d - 55)];
        es[(l + 1) * ESTRIDE + d] = v;
    }
    for (int i = threadIdx.x; i < ESTRIDE; i += 256) {
        es[i] = 0.f;
        es[129 * ESTRIDE + i] = 0.f;
    }
    __syncthreads();

    const int lane = threadIdx.x & 31;
    const int warp = threadIdx.x >> 5;

    for (int chunk = warp; chunk < HIDP / 8; chunk += 8) {
        const int c0 = chunk * 8;
        // acc2[j][p]: position j (lane + 32j), channel pair p (c0+2p, c0+2p+1)
        u64 acc2[4][4];
        #pragma unroll
        for (int j = 0; j < 4; j++)
            #pragma unroll
            for (int p = 0; p < 4; p++) acc2[j][p] = 0ull;

        #pragma unroll 1
        for (int d = 0; d < EMBD; d++) {
            // emb values for this thread's 4 positions x 3 taps (conflict-free LDS)
            float e[4][3];
            #pragma unroll
            for (int j = 0; j < 4; j++) {
                int rb = (lane + 32 * j) * ESTRIDE + d;
                e[j][0] = es[rb];
                e[j][1] = es[rb + ESTRIDE];
                e[j][2] = es[rb + 2 * ESTRIDE];
            }
            #pragma unroll
            for (int kk = 0; kk < 3; kk++) {
                // 8 channels = 4 packed f32x2 (16B-aligned: offset = 928*d'+32*chunk bytes)
                const ulonglong2* wp =
                    (const ulonglong2*)(g_wT + (d * 3 + kk) * HIDP + c0);
                ulonglong2 wA = wp[0], wB = wp[1];
                u64 w2[4] = { wA.x, wA.y, wB.x, wB.y };
                #pragma unroll
                for (int j = 0; j < 4; j++) {
                    u64 ee = splat_f32x2(e[j][kk]);
                    #pragma unroll
                    for (int p = 0; p < 4; p++)
                        ffma2(acc2[j][p], ee, w2[p]);
                }
            }
        }

        // unpack, max over 4 positions, then over 32 lanes (=128 positions); bias+relu
        #pragma unroll
        for (int p = 0; p < 4; p++) {
            float l0, h0, l1, h1, l2, h2, l3, h3;
            unpack2(acc2[0][p], l0, h0);
            unpack2(acc2[1][p], l1, h1);
            unpack2(acc2[2][p], l2, h2);
            unpack2(acc2[3][p], l3, h3);
            float mlo = fmaxf(fmaxf(l0, l1), fmaxf(l2, l3));
            float mhi = fmaxf(fmaxf(h0, h1), fmaxf(h2, h3));
            #pragma unroll
            for (int off = 16; off; off >>= 1) {
                mlo = fmaxf(mlo, __shfl_xor_sync(0xffffffffu, mlo, off));
                mhi = fmaxf(mhi, __shfl_xor_sync(0xffffffffu, mhi, off));
            }
            if (lane == 0) {
                int cg = c0 + 2 * p;
                float b0 = (cg     < HID) ? conv_b[cg]     : 0.f;
                float b1 = (cg + 1 < HID) ? conv_b[cg + 1] : 0.f;
                g_h[n * HIDP + cg]     = fmaxf(mlo + b0, 0.f);
                g_h[n * HIDP + cg + 1] = fmaxf(mhi + b1, 0.f);
            }
        }
    }
}

// ---------------------------------------------------------------------------
// Per-bag attention pooling + classifier. One block per bag (bag size <= 8).
// ---------------------------------------------------------------------------
__global__ __launch_bounds__(256) void bag_kernel(
    const int*   __restrict__ scope,
    const int*   __restrict__ relation,
    const float* __restrict__ rel_w,   // [NREL][HID]
    const float* __restrict__ rel_b,   // [NREL]
    float*       __restrict__ out)     // [NBAG][NREL]
{
    __shared__ float q[HID];
    __shared__ float rep[HID];
    __shared__ float logit[8];
    __shared__ float alpha[8];

    const int b   = blockIdx.x;
    const int rel = relation[b];
    const int s0  = scope[2 * b];
    int ns        = scope[2 * b + 1] - s0;
    if (ns > 8) ns = 8;

    for (int t = threadIdx.x; t < HID; t += 256) q[t] = rel_w[rel * HID + t];
    __syncthreads();

    const int lane = threadIdx.x & 31;
    const int warp = threadIdx.x >> 5;

    // logits: warp s computes dot(h[s0+s], q)
    {
        float p = 0.f;
        if (warp < ns) {
            const float* hr = g_h + (size_t)(s0 + warp) * HIDP;
            for (int c = lane; c < HID; c += 32) p += hr[c] * q[c];
        }
        #pragma unroll
        for (int off = 16; off; off >>= 1) p += __shfl_xor_sync(0xffffffffu, p, off);
        if (lane == 0 && warp < 8) logit[warp] = (warp < ns) ? p : -1e30f;
    }
    __syncthreads();

    // softmax over <=8 sentences (serial, trivial)
    if (threadIdx.x == 0) {
        float m = -1e30f;
        for (int s = 0; s < ns; s++) m = fmaxf(m, logit[s]);
        float den = 0.f;
        for (int s = 0; s < ns; s++) { float e = expf(logit[s] - m); alpha[s] = e; den += e; }
        float inv = 1.f / den;
        for (int s = 0; s < ns; s++) alpha[s] *= inv;
    }
    __syncthreads();

    // bag_rep = sum_s alpha[s] * h[s0+s]
    for (int t = threadIdx.x; t < HID; t += 256) {
        float r = 0.f;
        for (int s = 0; s < ns; s++)
            r = fmaf(alpha[s], g_h[(size_t)(s0 + s) * HIDP + t], r);
        rep[t] = r;
    }
    __syncthreads();

    // out[b][r] = rep . rel_w[r] + rel_b[r]
    for (int r = warp; r < NREL; r += 8) {
        float p = 0.f;
        const float* wr = rel_w + r * HID;
        for (int c = lane; c < HID; c += 32) p += rep[c] * wr[c];
        #pragma unroll
        for (int off = 16; off; off >>= 1) p += __shfl_xor_sync(0xffffffffu, p, off);
        if (lane == 0) out[b * NREL + r] = p + rel_b[r];
    }
}

// ---------------------------------------------------------------------------
// Inputs (metadata order): X, pos1, pos2, mask, length, scope, relation,
//   word_emb, pos1_emb, pos2_emb, conv_w, conv_b, rel_w, rel_b
// ---------------------------------------------------------------------------
extern "C" void kernel_launch(void* const* d_in, const int* in_sizes, int n_in,
                              void* d_out, int out_size)
{
    const int*   X        = (const int*)d_in[0];
    const int*   P1       = (const int*)d_in[1];
    const int*   P2       = (const int*)d_in[2];
    const int*   scope    = (const int*)d_in[5];
    const int*   relation = (const int*)d_in[6];
    const float* WE       = (const float*)d_in[7];
    const float* E1       = (const float*)d_in[8];
    const float* E2       = (const float*)d_in[9];
    const float* conv_w   = (const float*)d_in[10];
    const float* conv_b   = (const float*)d_in[11];
    const float* rel_w    = (const float*)d_in[12];
    const float* rel_b    = (const float*)d_in[13];
    float*       out      = (float*)d_out;

    prep_w_kernel<<<(TT * HIDP + 255) / 256, 256>>>(conv_w);
    conv_kernel<<<NSENT, 256>>>(X, P1, P2, WE, E1, E2, conv_b);
    bag_kernel<<<NBAG, 256>>>(scope, relation, rel_w, rel_b, out);
}

// round 4
// speedup vs baseline: 3.9142x; 3.9142x over previous
#include <cuda_runtime.h>
#include <cstdint>

#define NSENT 4000
#define LSEQ  128
#define EMBD  60
#define HID   230
#define NCPAD 264          // padded channels for smem B (264 % 32 words = 8 -> conflict-free)
#define HIDP  232          // g_h row stride
#define NBAG  500
#define NREL  25
#define GRID  148

// ---- smem layout (bytes) ----
#define WS_FLOATS (180 * NCPAD)            // 47520 floats = 190080 B
#define ES_FLOATS (130 * EMBD)             // 7800 floats  = 31200 B
#define OFF_ES    (WS_FLOATS)
#define OFF_WBUF  (WS_FLOATS + ES_FLOATS)  // 2*264 floats
#define SM_DYN    ((WS_FLOATS + ES_FLOATS + 2 * NCPAD) * 4)

// Device scratch
__device__ __align__(16) float g_wPrep[WS_FLOATS];   // [t*60+d][c] tf32-rounded, c>=230 zero
__device__ float g_h[NSENT * HIDP];

// ---- helpers ----
__device__ __forceinline__ float tf32r(float x) {
    uint32_t r;
    asm("cvt.rna.tf32.f32 %0, %1;" : "=r"(r) : "f"(x));
    return __uint_as_float(r);
}

#define MMA8(c, a, b0, b1)                                              \
    asm volatile("mma.sync.aligned.m16n8k8.row.col.f32.tf32.tf32.f32 "  \
        "{%0,%1,%2,%3}, {%4,%5,%6,%7}, {%8,%9}, {%0,%1,%2,%3};"         \
        : "+f"((c)[0]), "+f"((c)[1]), "+f"((c)[2]), "+f"((c)[3])        \
        : "r"((a)[0]), "r"((a)[1]), "r"((a)[2]), "r"((a)[3]),           \
          "r"(b0), "r"(b1))

#define MMA4(c, a, b0)                                                  \
    asm volatile("mma.sync.aligned.m16n8k4.row.col.f32.tf32.tf32.f32 "  \
        "{%0,%1,%2,%3}, {%4,%5}, {%6}, {%0,%1,%2,%3};"                  \
        : "+f"((c)[0]), "+f"((c)[1]), "+f"((c)[2]), "+f"((c)[3])        \
        : "r"((a)[0]), "r"((a)[1]), "r"((b0)))

// ---------------------------------------------------------------------------
// Prep: conv_w [HID][60][3] -> g_wPrep[(t*60+d)*264 + c] (tf32-rounded, padded)
// ---------------------------------------------------------------------------
__global__ void prep_w_kernel(const float* __restrict__ conv_w) {
    int i = blockIdx.x * blockDim.x + threadIdx.x;
    if (i >= WS_FLOATS) return;
    int row = i / NCPAD, c = i - row * NCPAD;
    int t = row / EMBD, d = row - t * EMBD;
    g_wPrep[i] = (c < HID) ? tf32r(conv_w[c * 180 + d * 3 + t]) : 0.f;
}

// ---------------------------------------------------------------------------
// Persistent fused conv: embed-gather + conv1d(k=3) + maxpool + relu, tf32 mma.sync
// grid=148, block=256 (8 warps: 2 m-groups x 4 n-groups)
// ---------------------------------------------------------------------------
__global__ __launch_bounds__(256, 1) void conv_mma_kernel(
    const int*   __restrict__ X,
    const int*   __restrict__ P1,
    const int*   __restrict__ P2,
    const float* __restrict__ WE,
    const float* __restrict__ E1,
    const float* __restrict__ E2,
    const float* __restrict__ conv_b)
{
    extern __shared__ float sm[];
    float* wS   = sm;                 // [180][264]
    float* es   = sm + OFF_ES;        // [130][60]  row r = position r-1
    float* wbuf = sm + OFF_WBUF;      // [2][264]

    const int tid  = threadIdx.x;
    const int lane = tid & 31;
    const int warp = tid >> 5;
    const int mg   = warp >> 2;       // 0..1
    const int ng   = warp & 3;        // 0..3
    const int l4   = lane & 3;
    const int lu   = lane >> 2;

    // ---- one-time: weights GMEM -> smem; zero pad rows of es ----
    {
        const float4* src = (const float4*)g_wPrep;
        float4* dst = (float4*)wS;
        for (int i = tid; i < WS_FLOATS / 4; i += 256) dst[i] = src[i];
        for (int i = tid; i < EMBD; i += 256) {
            es[i] = 0.f;
            es[129 * EMBD + i] = 0.f;
        }
    }

    // ---- gather helpers (thread t: row l = t>>1, half = t&1, 30 cols) ----
    const int gl   = tid >> 1;
    const int half = tid & 1;
    float v[30];

    // prefetch sentence n into regs
    auto prefetch = [&](int n) {
        int x = X[n * LSEQ + gl];
        if (half == 0) {
            const float* w = WE + x * 50;
            #pragma unroll
            for (int j = 0; j < 30; j++) v[j] = w[j];
        } else {
            const float* w = WE + x * 50 + 30;
            #pragma unroll
            for (int j = 0; j < 20; j++) v[j] = w[j];
            int p1 = P1[n * LSEQ + gl];
            int p2 = P2[n * LSEQ + gl];
            const float* e1 = E1 + p1 * 5;
            const float* e2 = E2 + p2 * 5;
            #pragma unroll
            for (int j = 0; j < 5; j++) v[20 + j] = e1[j];
            #pragma unroll
            for (int j = 0; j < 5; j++) v[25 + j] = e2[j];
        }
    };
    auto sts_emb = [&]() {
        float* dst = es + (gl + 1) * EMBD + half * 30;
        #pragma unroll
        for (int j = 0; j < 30; j++) dst[j] = tf32r(v[j]);
    };

    const int n0 = blockIdx.x;
    prefetch(n0);
    __syncthreads();          // weights staged
    sts_emb();
    __syncthreads();          // first sentence staged

    const uint32_t* esu = (const uint32_t*)es;
    const uint32_t* wSu = (const uint32_t*)wS;

    for (int n = n0; n < NSENT; n += GRID) {
        const int nn = n + GRID;
        if (nn < NSENT) prefetch(nn);     // LDGs fly during mma

        float acc[4][8][4];
        #pragma unroll
        for (int mt = 0; mt < 4; mt++)
            #pragma unroll
            for (int nt = 0; nt < 8; nt++)
                #pragma unroll
                for (int q = 0; q < 4; q++) acc[mt][nt][q] = 0.f;

        const int arow = mg * 64 + lu;    // +t per tap
        #pragma unroll 1
        for (int t = 0; t < 3; t++) {
            #pragma unroll 1
            for (int s = 0; s < 7; s++) {
                const int k0 = s * 8;
                uint32_t a[4][4];
                #pragma unroll
                for (int mt = 0; mt < 4; mt++) {
                    const uint32_t* ap = esu + (arow + t + mt * 16) * EMBD + k0 + l4;
                    a[mt][0] = ap[0];
                    a[mt][1] = ap[8 * EMBD];
                    a[mt][2] = ap[4];
                    a[mt][3] = ap[8 * EMBD + 4];
                }
                const uint32_t* bp = wSu + (t * 60 + k0 + l4) * NCPAD + ng * 64 + lu;
                #pragma unroll
                for (int nt = 0; nt < 8; nt++) {
                    uint32_t b0 = bp[nt * 8];
                    uint32_t b1 = bp[4 * NCPAD + nt * 8];
                    #pragma unroll
                    for (int mt = 0; mt < 4; mt++) MMA8(acc[mt][nt], a[mt], b0, b1);
                }
            }
            {   // k4 tail: cols 56..59
                uint32_t a[4][2];
                #pragma unroll
                for (int mt = 0; mt < 4; mt++) {
                    const uint32_t* ap = esu + (arow + t + mt * 16) * EMBD + 56 + l4;
                    a[mt][0] = ap[0];
                    a[mt][1] = ap[8 * EMBD];
                }
                const uint32_t* bp = wSu + (t * 60 + 56 + l4) * NCPAD + ng * 64 + lu;
                #pragma unroll
                for (int nt = 0; nt < 8; nt++) {
                    uint32_t b0 = bp[nt * 8];
                    #pragma unroll
                    for (int mt = 0; mt < 4; mt++) MMA4(acc[mt][nt], a[mt], b0);
                }
            }
        }

        // ---- epilogue: max over 128 rows, bias, relu -> g_h ----
        #pragma unroll
        for (int nt = 0; nt < 8; nt++) {
            float m0 = -1e30f, m1 = -1e30f;
            #pragma unroll
            for (int mt = 0; mt < 4; mt++) {
                m0 = fmaxf(m0, fmaxf(acc[mt][nt][0], acc[mt][nt][2]));
                m1 = fmaxf(m1, fmaxf(acc[mt][nt][1], acc[mt][nt][3]));
            }
            #pragma unroll
            for (int off = 4; off < 32; off <<= 1) {
                m0 = fmaxf(m0, __shfl_xor_sync(0xffffffffu, m0, off));
                m1 = fmaxf(m1, __shfl_xor_sync(0xffffffffu, m1, off));
            }
            if (lu == 0) {
                int c = ng * 64 + nt * 8 + l4 * 2;
                wbuf[mg * NCPAD + c]     = m0;
                wbuf[mg * NCPAD + c + 1] = m1;
            }
        }
        __syncthreads();
        if (tid < HIDP) {
            float m = fmaxf(wbuf[tid], wbuf[NCPAD + tid]);
            float b = (tid < HID) ? conv_b[tid] : 0.f;
            g_h[n * HIDP + tid] = fmaxf(m + b, 0.f);
        }
        __syncthreads();                  // es free to overwrite
        if (nn < NSENT) {
            sts_emb();
            __syncthreads();
        }
    }
}

// ---------------------------------------------------------------------------
// Per-bag attention pooling + classifier
// ---------------------------------------------------------------------------
__global__ __launch_bounds__(256) void bag_kernel(
    const int*   __restrict__ scope,
    const int*   __restrict__ relation,
    const float* __restrict__ rel_w,
    const float* __restrict__ rel_b,
    float*       __restrict__ out)
{
    __shared__ float q[HID];
    __shared__ float rep[HID];
    __shared__ float logit[8];
    __shared__ float alpha[8];

    const int b   = blockIdx.x;
    const int rel = relation[b];
    const int s0  = scope[2 * b];
    int ns        = scope[2 * b + 1] - s0;
    if (ns > 8) ns = 8;

    for (int t = threadIdx.x; t < HID; t += 256) q[t] = rel_w[rel * HID + t];
    __syncthreads();

    const int lane = threadIdx.x & 31;
    const int warp = threadIdx.x >> 5;

    {
        float p = 0.f;
        if (warp < ns) {
            const float* hr = g_h + (size_t)(s0 + warp) * HIDP;
            for (int c = lane; c < HID; c += 32) p += hr[c] * q[c];
        }
        #pragma unroll
        for (int off = 16; off; off >>= 1) p += __shfl_xor_sync(0xffffffffu, p, off);
        if (lane == 0 && warp < 8) logit[warp] = (warp < ns) ? p : -1e30f;
    }
    __syncthreads();

    if (threadIdx.x == 0) {
        float m = -1e30f;
        for (int s = 0; s < ns; s++) m = fmaxf(m, logit[s]);
        float den = 0.f;
        for (int s = 0; s < ns; s++) { float e = expf(logit[s] - m); alpha[s] = e; den += e; }
        float inv = 1.f / den;
        for (int s = 0; s < ns; s++) alpha[s] *= inv;
    }
    __syncthreads();

    for (int t = threadIdx.x; t < HID; t += 256) {
        float r = 0.f;
        for (int s = 0; s < ns; s++)
            r = fmaf(alpha[s], g_h[(size_t)(s0 + s) * HIDP + t], r);
        rep[t] = r;
    }
    __syncthreads();

    for (int r = warp; r < NREL; r += 8) {
        float p = 0.f;
        const float* wr = rel_w + r * HID;
        for (int c = lane; c < HID; c += 32) p += rep[c] * wr[c];
        #pragma unroll
        for (int off = 16; off; off >>= 1) p += __shfl_xor_sync(0xffffffffu, p, off);
        if (lane == 0) out[b * NREL + r] = p + rel_b[r];
    }
}

// ---------------------------------------------------------------------------
extern "C" void kernel_launch(void* const* d_in, const int* in_sizes, int n_in,
                              void* d_out, int out_size)
{
    const int*   X        = (const int*)d_in[0];
    const int*   P1       = (const int*)d_in[1];
    const int*   P2       = (const int*)d_in[2];
    const int*   scope    = (const int*)d_in[5];
    const int*   relation = (const int*)d_in[6];
    const float* WE       = (const float*)d_in[7];
    const float* E1       = (const float*)d_in[8];
    const float* E2       = (const float*)d_in[9];
    const float* conv_w   = (const float*)d_in[10];
    const float* conv_b   = (const float*)d_in[11];
    const float* rel_w    = (const float*)d_in[12];
    const float* rel_b    = (const float*)d_in[13];
    float*       out      = (float*)d_out;

    cudaFuncSetAttribute(conv_mma_kernel,
                         cudaFuncAttributeMaxDynamicSharedMemorySize, SM_DYN);

    prep_w_kernel<<<(WS_FLOATS + 255) / 256, 256>>>(conv_w);
    conv_mma_kernel<<<GRID, 256, SM_DYN>>>(X, P1, P2, WE, E1, E2, conv_b);
    bag_kernel<<<NBAG, 256>>>(scope, relation, rel_w, rel_b, out);
}

// round 5
// speedup vs baseline: 6.0185x; 1.5376x over previous
#include <cuda_runtime.h>
#include <cuda_fp16.h>
#include <cstdint>

#define NSENT 4000
#define LSEQ  128
#define EMBD  60
#define HID   230
#define HIDP  232          // g_h row stride
#define NBAG  500
#define NREL  25
#define GRID  148

#define NCH2  264          // padded channels (half2 cols per k-row; 264 mod 32 = 8 -> conflict-free)
#define ESW2  36           // es row stride in half2 words (36 mod 32 = 4 -> conflict-free)

// ---- smem layout (in 4-byte words) ----
#define W_WORDS  (3 * 32 * NCH2)            // 25344 words  (weights as half2)
#define ES_WORDS (130 * ESW2)               // 4680 words   (embeddings as half2)
#define OFF_ES   (W_WORDS)
#define OFF_WBUF (W_WORDS + ES_WORDS)       // 2*264 floats
#define SM_DYN   ((W_WORDS + ES_WORDS + 2 * NCH2) * 4)

// Device scratch
__device__ __align__(16) __half g_w2[3 * 32 * NCH2 * 2];  // [tap][kpair][c]{lo,hi}
__device__ float g_h[NSENT * HIDP];

#define MMAH(c, a, b0, b1)                                                  \
    asm volatile("mma.sync.aligned.m16n8k16.row.col.f32.f16.f16.f32 "       \
        "{%0,%1,%2,%3}, {%4,%5,%6,%7}, {%8,%9}, {%0,%1,%2,%3};"             \
        : "+f"((c)[0]), "+f"((c)[1]), "+f"((c)[2]), "+f"((c)[3])            \
        : "r"((a)[0]), "r"((a)[1]), "r"((a)[2]), "r"((a)[3]),               \
          "r"(b0), "r"(b1))

// ---------------------------------------------------------------------------
// Prep: conv_w [HID][60][3] -> g_w2[(tap*32+p)*528 + c*2 + parity] fp16
//   k = 2p+parity; zero pad k>=60 or c>=230
// ---------------------------------------------------------------------------
__global__ void prep_w_kernel(const float* __restrict__ conv_w) {
    int i = blockIdx.x * blockDim.x + threadIdx.x;
    if (i >= 3 * 32 * NCH2 * 2) return;
    int row = i / (NCH2 * 2), rem = i % (NCH2 * 2);
    int c = rem >> 1, parity = rem & 1;
    int tap = row >> 5, p = row & 31;
    int k = p * 2 + parity;
    float v = (c < HID && k < EMBD) ? conv_w[c * 180 + k * 3 + tap] : 0.f;
    g_w2[i] = __float2half(v);
}

// ---------------------------------------------------------------------------
// Persistent fused conv: embed-gather + conv1d(k=3) + maxpool + relu, fp16 mma.sync
// grid=148, block=256 (8 warps: 2 m-groups x 4 n-groups; warp tile 64x64)
// ---------------------------------------------------------------------------
__global__ __launch_bounds__(256, 1) void conv_mma_kernel(
    const int*   __restrict__ X,
    const int*   __restrict__ P1,
    const int*   __restrict__ P2,
    const float* __restrict__ WE,
    const float* __restrict__ E1,
    const float* __restrict__ E2,
    const float* __restrict__ conv_b)
{
    extern __shared__ uint32_t sm[];
    uint32_t* w2   = sm;               // [3*32][264] half2
    uint32_t* es2  = sm + OFF_ES;      // [130][36] half2; row r = position r-1
    float*    wbuf = (float*)(sm + OFF_WBUF);  // [2][264]

    const int tid  = threadIdx.x;
    const int lane = tid & 31;
    const int warp = tid >> 5;
    const int mg   = warp >> 2;        // 0..1
    const int ng   = warp & 3;         // 0..3
    const int l4   = lane & 3;
    const int lu   = lane >> 2;

    // ---- one-time: weights GMEM -> smem; zero all of es (covers pads) ----
    {
        const float4* src = (const float4*)g_w2;
        float4* dst = (float4*)w2;
        for (int i = tid; i < W_WORDS / 4; i += 256) dst[i] = src[i];
        for (int i = tid; i < ES_WORDS; i += 256) es2[i] = 0u;
    }

    // ---- gather (thread t: row l = t>>1, half = t&1, 30 emb values) ----
    const int gl   = tid >> 1;
    const int half = tid & 1;
    float v[30];

    auto prefetch = [&](int n) {
        int x = X[n * LSEQ + gl];
        if (half == 0) {
            const float* w = WE + x * 50;
            #pragma unroll
            for (int j = 0; j < 30; j++) v[j] = w[j];
        } else {
            const float* w = WE + x * 50 + 30;
            #pragma unroll
            for (int j = 0; j < 20; j++) v[j] = w[j];
            int p1 = P1[n * LSEQ + gl];
            int p2 = P2[n * LSEQ + gl];
            const float* e1 = E1 + p1 * 5;
            const float* e2 = E2 + p2 * 5;
            #pragma unroll
            for (int j = 0; j < 5; j++) v[20 + j] = e1[j];
            #pragma unroll
            for (int j = 0; j < 5; j++) v[25 + j] = e2[j];
        }
    };
    auto sts_emb = [&]() {
        uint32_t* dst = es2 + (gl + 1) * ESW2 + half * 15;
        #pragma unroll
        for (int j = 0; j < 15; j++) {
            __half2 h = __floats2half2_rn(v[2 * j], v[2 * j + 1]);
            dst[j] = *(uint32_t*)&h;
        }
    };

    const int n0 = blockIdx.x;
    prefetch(n0);
    __syncthreads();          // weights + es zeros staged
    sts_emb();
    __syncthreads();          // first sentence staged

    for (int n = n0; n < NSENT; n += GRID) {
        const int nn = n + GRID;
        if (nn < NSENT) prefetch(nn);     // LDGs fly during mma

        float acc[4][8][4];
        #pragma unroll
        for (int mt = 0; mt < 4; mt++)
            #pragma unroll
            for (int nt = 0; nt < 8; nt++)
                #pragma unroll
                for (int q = 0; q < 4; q++) acc[mt][nt][q] = 0.f;

        const int arow = mg * 64 + lu;    // + t + mt*16 per fragment
        #pragma unroll 1
        for (int t = 0; t < 3; t++) {
            #pragma unroll
            for (int ks = 0; ks < 4; ks++) {
                uint32_t a[4][4];
                #pragma unroll
                for (int mt = 0; mt < 4; mt++) {
                    const uint32_t* ap = es2 + (arow + t + mt * 16) * ESW2 + ks * 8 + l4;
                    a[mt][0] = ap[0];
                    a[mt][1] = ap[8 * ESW2];
                    a[mt][2] = ap[4];
                    a[mt][3] = ap[8 * ESW2 + 4];
                }
                const uint32_t* bp = w2 + (t * 32 + ks * 8 + l4) * NCH2 + ng * 64 + lu;
                #pragma unroll
                for (int nt = 0; nt < 8; nt++) {
                    uint32_t b0 = bp[nt * 8];
                    uint32_t b1 = bp[4 * NCH2 + nt * 8];
                    #pragma unroll
                    for (int mt = 0; mt < 4; mt++) MMAH(acc[mt][nt], a[mt], b0, b1);
                }
            }
        }

        // ---- epilogue: max over 128 rows, bias, relu -> g_h ----
        #pragma unroll
        for (int nt = 0; nt < 8; nt++) {
            float m0 = -1e30f, m1 = -1e30f;
            #pragma unroll
            for (int mt = 0; mt < 4; mt++) {
                m0 = fmaxf(m0, fmaxf(acc[mt][nt][0], acc[mt][nt][2]));
                m1 = fmaxf(m1, fmaxf(acc[mt][nt][1], acc[mt][nt][3]));
            }
            #pragma unroll
            for (int off = 4; off < 32; off <<= 1) {
                m0 = fmaxf(m0, __shfl_xor_sync(0xffffffffu, m0, off));
                m1 = fmaxf(m1, __shfl_xor_sync(0xffffffffu, m1, off));
            }
            if (lu == 0) {
                int c = ng * 64 + nt * 8 + l4 * 2;
                wbuf[mg * NCH2 + c]     = m0;
                wbuf[mg * NCH2 + c + 1] = m1;
            }
        }
        __syncthreads();
        if (tid < HIDP) {
            float m = fmaxf(wbuf[tid], wbuf[NCH2 + tid]);
            float b = (tid < HID) ? conv_b[tid] : 0.f;
            g_h[n * HIDP + tid] = fmaxf(m + b, 0.f);
        }
        __syncthreads();                  // es free to overwrite
        if (nn < NSENT) {
            sts_emb();
            __syncthreads();
        }
    }
}

// ---------------------------------------------------------------------------
// Per-bag attention pooling + classifier
// ---------------------------------------------------------------------------
__global__ __launch_bounds__(256) void bag_kernel(
    const int*   __restrict__ scope,
    const int*   __restrict__ relation,
    const float* __restrict__ rel_w,
    const float* __restrict__ rel_b,
    float*       __restrict__ out)
{
    __shared__ float q[HID];
    __shared__ float rep[HID];
    __shared__ float logit[8];
    __shared__ float alpha[8];

    const int b   = blockIdx.x;
    const int rel = relation[b];
    const int s0  = scope[2 * b];
    int ns        = scope[2 * b + 1] - s0;
    if (ns > 8) ns = 8;

    for (int t = threadIdx.x; t < HID; t += 256) q[t] = rel_w[rel * HID + t];
    __syncthreads();

    const int lane = threadIdx.x & 31;
    const int warp = threadIdx.x >> 5;

    {
        float p = 0.f;
        if (warp < ns) {
            const float* hr = g_h + (size_t)(s0 + warp) * HIDP;
            for (int c = lane; c < HID; c += 32) p += hr[c] * q[c];
        }
        #pragma unroll
        for (int off = 16; off; off >>= 1) p += __shfl_xor_sync(0xffffffffu, p, off);
        if (lane == 0 && warp < 8) logit[warp] = (warp < ns) ? p : -1e30f;
    }
    __syncthreads();

    if (threadIdx.x == 0) {
        float m = -1e30f;
        for (int s = 0; s < ns; s++) m = fmaxf(m, logit[s]);
        float den = 0.f;
        for (int s = 0; s < ns; s++) { float e = expf(logit[s] - m); alpha[s] = e; den += e; }
        float inv = 1.f / den;
        for (int s = 0; s < ns; s++) alpha[s] *= inv;
    }
    __syncthreads();

    for (int t = threadIdx.x; t < HID; t += 256) {
        float r = 0.f;
        for (int s = 0; s < ns; s++)
            r = fmaf(alpha[s], g_h[(size_t)(s0 + s) * HIDP + t], r);
        rep[t] = r;
    }
    __syncthreads();

    for (int r = warp; r < NREL; r += 8) {
        float p = 0.f;
        const float* wr = rel_w + r * HID;
        for (int c = lane; c < HID; c += 32) p += rep[c] * wr[c];
        #pragma unroll
        for (int off = 16; off; off >>= 1) p += __shfl_xor_sync(0xffffffffu, p, off);
        if (lane == 0) out[b * NREL + r] = p + rel_b[r];
    }
}

// ---------------------------------------------------------------------------
extern "C" void kernel_launch(void* const* d_in, const int* in_sizes, int n_in,
                              void* d_out, int out_size)
{
    const int*   X        = (const int*)d_in[0];
    const int*   P1       = (const int*)d_in[1];
    const int*   P2       = (const int*)d_in[2];
    const int*   scope    = (const int*)d_in[5];
    const int*   relation = (const int*)d_in[6];
    const float* WE       = (const float*)d_in[7];
    const float* E1       = (const float*)d_in[8];
    const float* E2       = (const float*)d_in[9];
    const float* conv_w   = (const float*)d_in[10];
    const float* conv_b   = (const float*)d_in[11];
    const float* rel_w    = (const float*)d_in[12];
    const float* rel_b    = (const float*)d_in[13];
    float*       out      = (float*)d_out;

    cudaFuncSetAttribute(conv_mma_kernel,
                         cudaFuncAttributeMaxDynamicSharedMemorySize, SM_DYN);

    prep_w_kernel<<<(3 * 32 * NCH2 * 2 + 255) / 256, 256>>>(conv_w);
    conv_mma_kernel<<<GRID, 256, SM_DYN>>>(X, P1, P2, WE, E1, E2, conv_b);
    bag_kernel<<<NBAG, 256>>>(scope, relation, rel_w, rel_b, out);
}

// round 6
// speedup vs baseline: 6.0980x; 1.0132x over previous
#include <cuda_runtime.h>
#include <cuda_fp16.h>
#include <cstdint>

#define NSENT 4000
#define LSEQ  128
#define EMBD  60
#define HID   230
#define HIDP  232
#define NBAG  500
#define NREL  25
#define GRID  148

#define ESW2   36                 // es row stride in half2 words (36 mod 32 = 4 -> LDSM conflict-free)
#define NCH    264                // padded channels (halves per B k-row)
#define WROWW  132                // B k-row stride in 4B words (132 mod 32 = 4 -> LDSM conflict-free)
#define WKROWS 192                // 3 taps x 64 padded k

// ---- smem layout (4-byte words) ----
#define W_WORDS  (WKROWS * WROWW)          // 25344
#define ES_WORDS (130 * ESW2)              // 4680
#define OFF_ES0  (W_WORDS)
#define OFF_ES1  (W_WORDS + ES_WORDS)
#define OFF_WBUF (W_WORDS + 2 * ES_WORDS)  // 2 bufs x 2 mg x 264 floats
#define SM_DYN   ((OFF_WBUF + 2 * 2 * NCH) * 4)

// Device scratch
__device__ __align__(16) __half g_wH[WKROWS * NCH];  // [tap*64+k][ch] halves
__device__ float g_h[NSENT * HIDP];

#define MMAH(c, a, b0, b1)                                                  \
    asm volatile("mma.sync.aligned.m16n8k16.row.col.f32.f16.f16.f32 "       \
        "{%0,%1,%2,%3}, {%4,%5,%6,%7}, {%8,%9}, {%0,%1,%2,%3};"             \
        : "+f"((c)[0]), "+f"((c)[1]), "+f"((c)[2]), "+f"((c)[3])            \
        : "r"((a)[0]), "r"((a)[1]), "r"((a)[2]), "r"((a)[3]),               \
          "r"(b0), "r"(b1))

#define LDSM4(d, addr)                                                       \
    asm volatile("ldmatrix.sync.aligned.m8n8.x4.shared.b16 {%0,%1,%2,%3}, [%4];" \
        : "=r"((d)[0]), "=r"((d)[1]), "=r"((d)[2]), "=r"((d)[3]) : "r"(addr))

#define LDSM4T(d, addr)                                                      \
    asm volatile("ldmatrix.sync.aligned.m8n8.x4.trans.shared.b16 {%0,%1,%2,%3}, [%4];" \
        : "=r"((d)[0]), "=r"((d)[1]), "=r"((d)[2]), "=r"((d)[3]) : "r"(addr))

__device__ __forceinline__ uint32_t smem_u32(const void* p) {
    uint32_t a;
    asm("{ .reg .u64 t; cvta.to.shared.u64 t, %1; cvt.u32.u64 %0, t; }" : "=r"(a) : "l"(p));
    return a;
}

// ---------------------------------------------------------------------------
// Prep: conv_w [HID][60][3] -> g_wH[(tap*64+k)*264 + c] halves (zero pad)
// ---------------------------------------------------------------------------
__global__ void prep_w_kernel(const float* __restrict__ conv_w) {
    int i = blockIdx.x * blockDim.x + threadIdx.x;
    if (i >= WKROWS * NCH) return;
    int row = i / NCH, c = i - row * NCH;
    int tap = row >> 6, k = row & 63;
    float v = (c < HID && k < EMBD) ? conv_w[c * 180 + k * 3 + tap] : 0.f;
    g_wH[i] = __float2half(v);
}

// ---------------------------------------------------------------------------
// Persistent fused conv: gather + conv1d(k=3) + maxpool + relu, fp16 mma + ldmatrix
// grid=148, block=256 (8 warps: 2 m-groups x 4 n-groups; warp tile 64x64)
// ---------------------------------------------------------------------------
__global__ __launch_bounds__(256, 1) void conv_mma_kernel(
    const int*   __restrict__ X,
    const int*   __restrict__ P1,
    const int*   __restrict__ P2,
    const float* __restrict__ WE,
    const float* __restrict__ E1,
    const float* __restrict__ E2,
    const float* __restrict__ conv_b)
{
    extern __shared__ uint32_t sm[];
    const uint32_t sb = smem_u32(sm);
    float* wbuf = (float*)(sm + OFF_WBUF);     // [2 buf][2 mg][264]

    const int tid  = threadIdx.x;
    const int lane = tid & 31;
    const int warp = tid >> 5;
    const int mg   = warp >> 2;
    const int ng   = warp & 3;
    const int l4   = lane & 3;
    const int lu   = lane >> 2;

    // ---- one-time: weights -> smem; zero both es buffers ----
    {
        const float4* src = (const float4*)g_wH;
        float4* dst = (float4*)sm;
        for (int i = tid; i < W_WORDS / 4; i += 256) dst[i] = src[i];
        for (int i = tid; i < 2 * ES_WORDS; i += 256) sm[OFF_ES0 + i] = 0u;
    }

    // ---- gather (thread t: row l = t>>1, half = t&1, 30 emb values) ----
    const int gl   = tid >> 1;
    const int half = tid & 1;
    float v[30];

    auto prefetch = [&](int n) {
        int x = X[n * LSEQ + gl];
        if (half == 0) {
            const float* w = WE + x * 50;
            #pragma unroll
            for (int j = 0; j < 30; j++) v[j] = w[j];
        } else {
            const float* w = WE + x * 50 + 30;
            #pragma unroll
            for (int j = 0; j < 20; j++) v[j] = w[j];
            int p1 = P1[n * LSEQ + gl];
            int p2 = P2[n * LSEQ + gl];
            const float* e1 = E1 + p1 * 5;
            const float* e2 = E2 + p2 * 5;
            #pragma unroll
            for (int j = 0; j < 5; j++) v[20 + j] = e1[j];
            #pragma unroll
            for (int j = 0; j < 5; j++) v[25 + j] = e2[j];
        }
    };
    auto sts_emb = [&](int esoff) {
        uint32_t* dst = sm + esoff + (gl + 1) * ESW2 + half * 15;
        #pragma unroll
        for (int j = 0; j < 15; j++) {
            __half2 h = __floats2half2_rn(v[2 * j], v[2 * j + 1]);
            dst[j] = *(uint32_t*)&h;
        }
    };

    // ---- per-lane LDSM address components ----
    const int a_row  = mg * 64 + (lane & 15);      // + t + mt*16
    const int a_ksel = (lane >> 4) * 4;            // k-half offset in words
    const int b_krow = (lane & 15);                // k row 0..15 within kstep
    const int b_nsel = (lane >> 4) * 4;            // channel-half offset in words
    const int b_chw  = ng * 32;                    // channel base in words

    const int n0 = blockIdx.x;
    prefetch(n0);
    __syncthreads();              // weights + zeros visible
    sts_emb(OFF_ES0);
    __syncthreads();              // first sentence staged

    int cur = 0;
    for (int n = n0; n < NSENT; n += GRID) {
        const int nn = n + GRID;
        if (nn < NSENT) prefetch(nn);          // LDGs fly under the MMAs

        const int esoff = cur ? OFF_ES1 : OFF_ES0;

        float acc[4][8][4];
        #pragma unroll
        for (int mt = 0; mt < 4; mt++)
            #pragma unroll
            for (int nt = 0; nt < 8; nt++)
                #pragma unroll
                for (int q = 0; q < 4; q++) acc[mt][nt][q] = 0.f;

        #pragma unroll 1
        for (int t = 0; t < 3; t++) {
            #pragma unroll
            for (int ks = 0; ks < 4; ks++) {
                uint32_t a[4][4];
                #pragma unroll
                for (int mt = 0; mt < 4; mt++) {
                    uint32_t ad = sb + ((esoff + (a_row + t + mt * 16) * ESW2
                                         + ks * 8 + a_ksel) << 2);
                    LDSM4(a[mt], ad);
                }
                const int krow0 = t * 64 + ks * 16 + b_krow;
                #pragma unroll
                for (int pr = 0; pr < 4; pr++) {
                    uint32_t b[4];
                    uint32_t bd = sb + ((krow0 * WROWW + b_chw + pr * 8 + b_nsel) << 2);
                    LDSM4T(b, bd);
                    #pragma unroll
                    for (int mt = 0; mt < 4; mt++) {
                        MMAH(acc[mt][2 * pr],     a[mt], b[0], b[1]);
                        MMAH(acc[mt][2 * pr + 1], a[mt], b[2], b[3]);
                    }
                }
            }
        }

        // ---- epilogue: max over rows -> wbuf[cur]; stage next sentence ----
        float* wb = wbuf + cur * 2 * NCH;
        #pragma unroll
        for (int nt = 0; nt < 8; nt++) {
            float m0 = -1e30f, m1 = -1e30f;
            #pragma unroll
            for (int mt = 0; mt < 4; mt++) {
                m0 = fmaxf(m0, fmaxf(acc[mt][nt][0], acc[mt][nt][2]));
                m1 = fmaxf(m1, fmaxf(acc[mt][nt][1], acc[mt][nt][3]));
            }
            #pragma unroll
            for (int off = 4; off < 32; off <<= 1) {
                m0 = fmaxf(m0, __shfl_xor_sync(0xffffffffu, m0, off));
                m1 = fmaxf(m1, __shfl_xor_sync(0xffffffffu, m1, off));
            }
            if (lu == 0) {
                int c = ng * 64 + nt * 8 + l4 * 2;
                wb[mg * NCH + c]     = m0;
                wb[mg * NCH + c + 1] = m1;
            }
        }
        if (nn < NSENT) sts_emb(cur ? OFF_ES0 : OFF_ES1);
        __syncthreads();          // wbuf[cur] + es[next] visible to all

        if (tid < HIDP) {
            float m = fmaxf(wb[tid], wb[NCH + tid]);
            float b = (tid < HID) ? conv_b[tid] : 0.f;
            g_h[n * HIDP + tid] = fmaxf(m + b, 0.f);
        }
        cur ^= 1;                 // next MMA block reads es[next]; wbuf ping-pongs
    }
}

// ---------------------------------------------------------------------------
// Per-bag attention pooling + classifier
// ---------------------------------------------------------------------------
__global__ __launch_bounds__(256) void bag_kernel(
    const int*   __restrict__ scope,
    const int*   __restrict__ relation,
    const float* __restrict__ rel_w,
    const float* __restrict__ rel_b,
    float*       __restrict__ out)
{
    __shared__ float q[HID];
    __shared__ float rep[HID];
    __shared__ float logit[8];
    __shared__ float alpha[8];

    const int b   = blockIdx.x;
    const int rel = relation[b];
    const int s0  = scope[2 * b];
    int ns        = scope[2 * b + 1] - s0;
    if (ns > 8) ns = 8;

    for (int t = threadIdx.x; t < HID; t += 256) q[t] = rel_w[rel * HID + t];
    __syncthreads();

    const int lane = threadIdx.x & 31;
    const int warp = threadIdx.x >> 5;

    {
        float p = 0.f;
        if (warp < ns) {
            const float* hr = g_h + (size_t)(s0 + warp) * HIDP;
            for (int c = lane; c < HID; c += 32) p += hr[c] * q[c];
        }
        #pragma unroll
        for (int off = 16; off; off >>= 1) p += __shfl_xor_sync(0xffffffffu, p, off);
        if (lane == 0 && warp < 8) logit[warp] = (warp < ns) ? p : -1e30f;
    }
    __syncthreads();

    if (threadIdx.x == 0) {
        float m = -1e30f;
        for (int s = 0; s < ns; s++) m = fmaxf(m, logit[s]);
        float den = 0.f;
        for (int s = 0; s < ns; s++) { float e = expf(logit[s] - m); alpha[s] = e; den += e; }
        float inv = 1.f / den;
        for (int s = 0; s < ns; s++) alpha[s] *= inv;
    }
    __syncthreads();

    for (int t = threadIdx.x; t < HID; t += 256) {
        float r = 0.f;
        for (int s = 0; s < ns; s++)
            r = fmaf(alpha[s], g_h[(size_t)(s0 + s) * HIDP + t], r);
        rep[t] = r;
    }
    __syncthreads();

    for (int r = warp; r < NREL; r += 8) {
        float p = 0.f;
        const float* wr = rel_w + r * HID;
        for (int c = lane; c < HID; c += 32) p += rep[c] * wr[c];
        #pragma unroll
        for (int off = 16; off; off >>= 1) p += __shfl_xor_sync(0xffffffffu, p, off);
        if (lane == 0) out[b * NREL + r] = p + rel_b[r];
    }
}

// ---------------------------------------------------------------------------
extern "C" void kernel_launch(void* const* d_in, const int* in_sizes, int n_in,
                              void* d_out, int out_size)
{
    const int*   X        = (const int*)d_in[0];
    const int*   P1       = (const int*)d_in[1];
    const int*   P2       = (const int*)d_in[2];
    const int*   scope    = (const int*)d_in[5];
    const int*   relation = (const int*)d_in[6];
    const float* WE       = (const float*)d_in[7];
    const float* E1       = (const float*)d_in[8];
    const float* E2       = (const float*)d_in[9];
    const float* conv_w   = (const float*)d_in[10];
    const float* conv_b   = (const float*)d_in[11];
    const float* rel_w    = (const float*)d_in[12];
    const float* rel_b    = (const float*)d_in[13];
    float*       out      = (float*)d_out;

    cudaFuncSetAttribute(conv_mma_kernel,
                         cudaFuncAttributeMaxDynamicSharedMemorySize, SM_DYN);

    prep_w_kernel<<<(WKROWS * NCH + 255) / 256, 256>>>(conv_w);
    conv_mma_kernel<<<GRID, 256, SM_DYN>>>(X, P1, P2, WE, E1, E2, conv_b);
    bag_kernel<<<NBAG, 256>>>(scope, relation, rel_w, rel_b, out);
}